// round 1
// baseline (speedup 1.0000x reference)
#include <cuda_runtime.h>
#include <math.h>

// Problem constants
#define NB      8192        // batch
#define CELLS   49
#define CH      30
#define ROW     (CELLS*CH)  // 1470 floats per image per tensor
#define MAXBOX  98

// Scratch for per-batch partial sums, SoA: comp*NB + b
// comp: 0=noobj, 1=cls, 2=coord, 3=obj
__device__ float g_part[4 * NB];

__global__ void __launch_bounds__(256, 4)
yolo_k1(const float* __restrict__ pred, const float* __restrict__ targ)
{
    __shared__ float sp[ROW];
    __shared__ float st[ROW];
    __shared__ int   s_bidx[MAXBOX];
    __shared__ unsigned char s_cmask[MAXBOX];
    __shared__ int   s_m;
    __shared__ float s_pxy[MAXBOX][4];
    __shared__ float s_txy[MAXBOX][4];
    __shared__ float s_red[4][8];

    const int b   = blockIdx.x;
    const int tid = threadIdx.x;

    // ---- coalesced load: 1470 floats = 735 float2 per tensor ----
    {
        const float2* p2 = reinterpret_cast<const float2*>(pred + (size_t)b * ROW);
        const float2* t2 = reinterpret_cast<const float2*>(targ + (size_t)b * ROW);
        float2* sp2 = reinterpret_cast<float2*>(sp);
        float2* st2 = reinterpret_cast<float2*>(st);
        #pragma unroll
        for (int i = tid; i < ROW / 2; i += 256) {
            sp2[i] = p2[i];
            st2[i] = t2[i];
        }
    }
    __syncthreads();

    // ---- compact masked boxes (object cells -> 2 boxes each) ----
    if (tid == 0) {
        int m = 0;
        #pragma unroll 7
        for (int c = 0; c < CELLS; c++) {
            if (st[c * CH + 4] > 0.0f) {
                s_bidx[m++] = 2 * c;
                s_bidx[m++] = 2 * c + 1;
            }
        }
        s_m = m;
    }
    __syncthreads();
    const int m = s_m;

    // ---- xyxy for masked boxes ----
    for (int l = tid; l < m; l += 256) {
        const int k   = s_bidx[l];
        const int off = (k >> 1) * CH + (k & 1) * 5;
        float cx = sp[off + 0], cy = sp[off + 1];
        float w  = sp[off + 2], h  = sp[off + 3];
        s_pxy[l][0] = cx - 0.5f * w;  s_pxy[l][1] = cy - 0.5f * h;
        s_pxy[l][2] = cx + 0.5f * w;  s_pxy[l][3] = cy + 0.5f * h;
        cx = st[off + 0]; cy = st[off + 1];
        w  = st[off + 2]; h  = st[off + 3];
        s_txy[l][0] = cx - 0.5f * w;  s_txy[l][1] = cy - 0.5f * h;
        s_txy[l][2] = cx + 0.5f * w;  s_txy[l][3] = cy + 0.5f * h;
    }
    __syncthreads();

    // ---- cmask[j] = any masked pred box with positive-overlap with target box j
    // (iou>0 <=> intersection>0; no division needed, matches max_iou != 0) ----
    for (int j = tid; j < m; j += 256) {
        const float tx0 = s_txy[j][0], ty0 = s_txy[j][1];
        const float tx1 = s_txy[j][2], ty1 = s_txy[j][3];
        bool any = false;
        for (int i = 0; i < m; i++) {
            const float lx = fmaxf(s_pxy[i][0], tx0);
            const float ly = fmaxf(s_pxy[i][1], ty0);
            const float rx = fminf(s_pxy[i][2], tx1);
            const float ry = fminf(s_pxy[i][3], ty1);
            if (rx > lx && ry > ly) { any = true; break; }
        }
        s_cmask[j] = any ? 1 : 0;
    }
    __syncthreads();

    // ---- per-thread partial losses ----
    float a_noobj = 0.0f, a_cls = 0.0f, a_coord = 0.0f, a_obj = 0.0f;

    for (int c = tid; c < CELLS; c += 256) {
        const float* pc = sp + c * CH;
        const float* tc = st + c * CH;
        const float conf = tc[4];
        if (conf == 0.0f) {
            const float d4 = pc[4];            // target conf == 0
            const float d9 = pc[9] - tc[9];
            a_noobj += d4 * d4 + d9 * d9;
        } else {
            float s = 0.0f;
            #pragma unroll
            for (int k = 10; k < CH; k++) {
                const float d = pc[k] - tc[k];
                s += d * d;
            }
            a_cls += s;
        }
    }

    for (int l = tid; l < m; l += 256) {
        if (s_cmask[l]) {
            const int k   = s_bidx[l];
            const int off = (k >> 1) * CH + (k & 1) * 5;
            const float dx = sp[off + 0] - st[off + 0];
            const float dy = sp[off + 1] - st[off + 1];
            const float dw = sqrtf(sp[off + 2]) - sqrtf(st[off + 2]);
            const float dh = sqrtf(sp[off + 3]) - sqrtf(st[off + 3]);
            const float dc = sp[off + 4] - st[off + 4];
            a_coord += dx * dx + dy * dy + dw * dw + dh * dh;
            a_obj   += dc * dc;
        }
    }

    // ---- deterministic block reduction: warp shuffle + smem tree ----
    #pragma unroll
    for (int o = 16; o > 0; o >>= 1) {
        a_noobj += __shfl_xor_sync(0xffffffffu, a_noobj, o);
        a_cls   += __shfl_xor_sync(0xffffffffu, a_cls,   o);
        a_coord += __shfl_xor_sync(0xffffffffu, a_coord, o);
        a_obj   += __shfl_xor_sync(0xffffffffu, a_obj,   o);
    }
    const int wid  = tid >> 5;
    const int lane = tid & 31;
    if (lane == 0) {
        s_red[0][wid] = a_noobj;
        s_red[1][wid] = a_cls;
        s_red[2][wid] = a_coord;
        s_red[3][wid] = a_obj;
    }
    __syncthreads();
    if (tid == 0) {
        float n = 0.f, c = 0.f, co = 0.f, ob = 0.f;
        #pragma unroll
        for (int w = 0; w < 8; w++) {
            n  += s_red[0][w];
            c  += s_red[1][w];
            co += s_red[2][w];
            ob += s_red[3][w];
        }
        g_part[0 * NB + b] = n;
        g_part[1 * NB + b] = c;
        g_part[2 * NB + b] = co;
        g_part[3 * NB + b] = ob;
    }
}

__global__ void __launch_bounds__(256)
yolo_k2(float* __restrict__ out)
{
    __shared__ double sred[256];
    __shared__ double comp_sum[4];
    const int t = threadIdx.x;

    for (int comp = 0; comp < 4; comp++) {
        double s = 0.0;
        for (int i = t; i < NB; i += 256)
            s += (double)g_part[comp * NB + i];
        sred[t] = s;
        __syncthreads();
        #pragma unroll
        for (int o = 128; o > 0; o >>= 1) {
            if (t < o) sred[t] += sred[t + o];
            __syncthreads();
        }
        if (t == 0) comp_sum[comp] = sred[0];
        __syncthreads();
    }

    if (t == 0) {
        const double Bd    = (double)NB;
        const double noobj = comp_sum[0];
        const double cls   = comp_sum[1];
        const double coord = comp_sum[2];
        const double obj   = comp_sum[3];
        const double cls_l   = cls / Bd;
        const double obj_l   = (obj + 0.5 * noobj) / Bd;
        const double coord_l = coord * 5.0 / Bd;
        out[0] = (float)(cls_l + obj_l + coord_l);
        out[1] = (float)cls_l;
        out[2] = (float)obj_l;
        out[3] = (float)coord_l;
    }
}

extern "C" void kernel_launch(void* const* d_in, const int* in_sizes, int n_in,
                              void* d_out, int out_size)
{
    const float* pred = (const float*)d_in[0];
    const float* targ = (const float*)d_in[1];
    float* out = (float*)d_out;

    yolo_k1<<<NB, 256>>>(pred, targ);
    yolo_k2<<<1, 256>>>(out);
}

// round 5
// speedup vs baseline: 1.1169x; 1.1169x over previous
#include <cuda_runtime.h>
#include <math.h>

#define NB      8192
#define CELLS   49
#define CH      30
#define ROW     (CELLS*CH)   // 1470 floats
#define MAXBOX  98

// Per-batch partial sums: {noobj, cls, coord, obj} as one float4, coalesced.
__device__ float4 g_part4[NB];

__global__ void __launch_bounds__(128)
yolo_k1(const float* __restrict__ pred, const float* __restrict__ targ)
{
    __shared__ float  sp[ROW];
    __shared__ float  st[ROW];
    __shared__ float4 s_pbox[MAXBOX];     // pred boxes xyxy; unmasked -> empty box
    __shared__ float  s_red[4][4];

    const int b   = blockIdx.x;
    const int tid = threadIdx.x;

    // ---- coalesced load: 735 float2 per tensor ----
    {
        const float2* p2 = reinterpret_cast<const float2*>(pred + (size_t)b * ROW);
        const float2* t2 = reinterpret_cast<const float2*>(targ + (size_t)b * ROW);
        float2* sp2 = reinterpret_cast<float2*>(sp);
        float2* st2 = reinterpret_cast<float2*>(st);
        #pragma unroll
        for (int i = tid; i < ROW / 2; i += 128) {
            sp2[i] = p2[i];
            st2[i] = t2[i];
        }
    }
    __syncthreads();

    float a_noobj = 0.0f, a_cls = 0.0f, a_coord = 0.0f, a_obj = 0.0f;

    // ---- pred boxes -> smem (empty box if cell unmasked; no compaction) ----
    bool  mymask = false;
    int   myoff  = 0;
    if (tid < MAXBOX) {
        const int c = tid >> 1;
        myoff  = c * CH + (tid & 1) * 5;
        mymask = st[c * CH + 4] > 0.0f;
        float4 box;
        if (mymask) {
            const float cx = sp[myoff + 0], cy = sp[myoff + 1];
            const float w  = sp[myoff + 2], h  = sp[myoff + 3];
            box = make_float4(cx - 0.5f * w, cy - 0.5f * h,
                              cx + 0.5f * w, cy + 0.5f * h);
        } else {
            box = make_float4(1e30f, 1e30f, -1e30f, -1e30f);  // never overlaps
        }
        s_pbox[tid] = box;
    }

    // ---- per-cell losses (independent of s_pbox; before the barrier) ----
    if (tid < CELLS) {
        const float* pc = sp + tid * CH;
        const float* tc = st + tid * CH;
        if (tc[4] == 0.0f) {
            const float d4 = pc[4];             // target conf == 0
            const float d9 = pc[9] - tc[9];
            a_noobj = d4 * d4 + d9 * d9;
        } else {
            float s = 0.0f;
            #pragma unroll
            for (int k = 10; k < CH; k++) {
                const float d = pc[k] - tc[k];
                s += d * d;
            }
            a_cls = s;
        }
    }
    __syncthreads();

    // ---- cmask + coord/obj losses (thread j owns target box j) ----
    if (tid < MAXBOX && mymask) {
        const float tcx = st[myoff + 0], tcy = st[myoff + 1];
        const float tw  = st[myoff + 2], th  = st[myoff + 3];
        const float tx0 = tcx - 0.5f * tw, ty0 = tcy - 0.5f * th;
        const float tx1 = tcx + 0.5f * tw, ty1 = tcy + 0.5f * th;
        bool any = false;
        for (int i = 0; i < MAXBOX; i++) {
            const float4 pb = s_pbox[i];       // broadcast across lanes (N=1)
            const float lx = fmaxf(pb.x, tx0);
            const float ly = fmaxf(pb.y, ty0);
            const float rx = fminf(pb.z, tx1);
            const float ry = fminf(pb.w, ty1);
            if (rx > lx && ry > ly) { any = true; break; }
        }
        if (any) {
            const float dx = sp[myoff + 0] - st[myoff + 0];
            const float dy = sp[myoff + 1] - st[myoff + 1];
            const float dw = sqrtf(sp[myoff + 2]) - sqrtf(st[myoff + 2]);
            const float dh = sqrtf(sp[myoff + 3]) - sqrtf(st[myoff + 3]);
            const float dc = sp[myoff + 4] - st[myoff + 4];
            a_coord = dx * dx + dy * dy + dw * dw + dh * dh;
            a_obj   = dc * dc;
        }
    }

    // ---- deterministic reduction: warp shuffle + 4-warp smem stage ----
    #pragma unroll
    for (int o = 16; o > 0; o >>= 1) {
        a_noobj += __shfl_xor_sync(0xffffffffu, a_noobj, o);
        a_cls   += __shfl_xor_sync(0xffffffffu, a_cls,   o);
        a_coord += __shfl_xor_sync(0xffffffffu, a_coord, o);
        a_obj   += __shfl_xor_sync(0xffffffffu, a_obj,   o);
    }
    const int wid  = tid >> 5;
    const int lane = tid & 31;
    if (lane == 0) {
        s_red[0][wid] = a_noobj;
        s_red[1][wid] = a_cls;
        s_red[2][wid] = a_coord;
        s_red[3][wid] = a_obj;
    }
    __syncthreads();
    if (tid == 0) {
        float4 r;
        r.x = s_red[0][0] + s_red[0][1] + s_red[0][2] + s_red[0][3];
        r.y = s_red[1][0] + s_red[1][1] + s_red[1][2] + s_red[1][3];
        r.z = s_red[2][0] + s_red[2][1] + s_red[2][2] + s_red[2][3];
        r.w = s_red[3][0] + s_red[3][1] + s_red[3][2] + s_red[3][3];
        g_part4[b] = r;
    }
}

__global__ void __launch_bounds__(1024)
yolo_k2(float* __restrict__ out)
{
    __shared__ double s_red[4][32];
    const int t    = threadIdx.x;
    const int wid  = t >> 5;
    const int lane = t & 31;

    // 8 independent float4 loads per thread (coalesced, L2-resident)
    double n = 0.0, c = 0.0, co = 0.0, ob = 0.0;
    #pragma unroll
    for (int i = t; i < NB; i += 1024) {
        const float4 v = g_part4[i];
        n  += (double)v.x;
        c  += (double)v.y;
        co += (double)v.z;
        ob += (double)v.w;
    }

    #pragma unroll
    for (int o = 16; o > 0; o >>= 1) {
        n  += __shfl_xor_sync(0xffffffffu, n,  o);
        c  += __shfl_xor_sync(0xffffffffu, c,  o);
        co += __shfl_xor_sync(0xffffffffu, co, o);
        ob += __shfl_xor_sync(0xffffffffu, ob, o);
    }
    if (lane == 0) {
        s_red[0][wid] = n;
        s_red[1][wid] = c;
        s_red[2][wid] = co;
        s_red[3][wid] = ob;
    }
    __syncthreads();
    if (t == 0) {
        double sn = 0.0, sc = 0.0, sco = 0.0, sob = 0.0;
        #pragma unroll
        for (int w = 0; w < 32; w++) {
            sn  += s_red[0][w];
            sc  += s_red[1][w];
            sco += s_red[2][w];
            sob += s_red[3][w];
        }
        const double Bd      = (double)NB;
        const double cls_l   = sc / Bd;
        const double obj_l   = (sob + 0.5 * sn) / Bd;
        const double coord_l = sco * 5.0 / Bd;
        out[0] = (float)(cls_l + obj_l + coord_l);
        out[1] = (float)cls_l;
        out[2] = (float)obj_l;
        out[3] = (float)coord_l;
    }
}

extern "C" void kernel_launch(void* const* d_in, const int* in_sizes, int n_in,
                              void* d_out, int out_size)
{
    const float* pred = (const float*)d_in[0];
    const float* targ = (const float*)d_in[1];
    float* out = (float*)d_out;

    yolo_k1<<<NB, 128>>>(pred, targ);
    yolo_k2<<<1, 1024>>>(out);
}

// round 6
// speedup vs baseline: 1.7220x; 1.5417x over previous
#include <cuda_runtime.h>
#include <math.h>

#define NB        8192
#define CELLS     49
#define CH        30
#define ROW       (CELLS*CH)     // 1470 floats per image
#define PAIR_ROW  (2*ROW)        // 2940 floats per CTA (2 images)
#define MAXBOX    98
#define NPART     (NB/2)         // 4096 pair-partials
#define NMID      32

// Stage-1 partials: one float4 {noobj, cls, coord, obj} per image-pair.
__device__ float4  g_part4[NPART];
// Stage-2 partials: 32 double4.
__device__ double4 g_mid[NMID];

__global__ void __launch_bounds__(256)
yolo_k1(const float* __restrict__ pred, const float* __restrict__ targ)
{
    __shared__ float  sp[PAIR_ROW];
    __shared__ float  st[PAIR_ROW];
    __shared__ float4 s_pbox[2][MAXBOX];   // pred boxes xyxy per sub-batch
    __shared__ float  s_red[4][8];

    const int tid = threadIdx.x;

    // ---- coalesced float4 load: 735 float4 per tensor (16B-aligned base) ----
    {
        const float4* p4 = reinterpret_cast<const float4*>(pred + (size_t)blockIdx.x * PAIR_ROW);
        const float4* t4 = reinterpret_cast<const float4*>(targ + (size_t)blockIdx.x * PAIR_ROW);
        float4* sp4 = reinterpret_cast<float4*>(sp);
        float4* st4 = reinterpret_cast<float4*>(st);
        const int i0 = tid, i1 = tid + 256, i2 = tid + 512;
        // front-batch loads for MLP
        float4 a0 = p4[i0], b0 = t4[i0];
        float4 a1, b1, a2, b2;
        if (i1 < PAIR_ROW/4) { a1 = p4[i1]; b1 = t4[i1]; }
        if (i2 < PAIR_ROW/4) { a2 = p4[i2]; b2 = t4[i2]; }
        sp4[i0] = a0; st4[i0] = b0;
        if (i1 < PAIR_ROW/4) { sp4[i1] = a1; st4[i1] = b1; }
        if (i2 < PAIR_ROW/4) { sp4[i2] = a2; st4[i2] = b2; }
    }
    __syncthreads();

    const int sub  = tid >> 7;        // 0 or 1: which image of the pair
    const int lt   = tid & 127;       // local thread within sub-group
    const int base = sub * ROW;

    float a_noobj = 0.0f, a_cls = 0.0f, a_coord = 0.0f, a_obj = 0.0f;

    // ---- pred boxes -> smem (empty box if cell unmasked; no compaction) ----
    bool mymask = false;
    int  myoff  = 0;
    if (lt < MAXBOX) {
        const int c = lt >> 1;
        myoff  = base + c * CH + (lt & 1) * 5;
        mymask = st[base + c * CH + 4] > 0.0f;
        float4 box;
        if (mymask) {
            const float cx = sp[myoff + 0], cy = sp[myoff + 1];
            const float w  = sp[myoff + 2], h  = sp[myoff + 3];
            box = make_float4(cx - 0.5f * w, cy - 0.5f * h,
                              cx + 0.5f * w, cy + 0.5f * h);
        } else {
            box = make_float4(1e30f, 1e30f, -1e30f, -1e30f);  // never overlaps
        }
        s_pbox[sub][lt] = box;
    }

    // ---- per-cell losses (independent of s_pbox; before the barrier) ----
    if (lt < CELLS) {
        const float* pc = sp + base + lt * CH;
        const float* tc = st + base + lt * CH;
        if (tc[4] == 0.0f) {
            const float d4 = pc[4];              // target conf == 0
            const float d9 = pc[9] - tc[9];
            a_noobj = d4 * d4 + d9 * d9;
        } else {
            float s = 0.0f;
            #pragma unroll
            for (int k = 10; k < CH; k++) {
                const float d = pc[k] - tc[k];
                s += d * d;
            }
            a_cls = s;
        }
    }
    __syncthreads();

    // ---- cmask + coord/obj losses (thread j owns target box j) ----
    if (lt < MAXBOX && mymask) {
        const float tcx = st[myoff + 0], tcy = st[myoff + 1];
        const float tw  = st[myoff + 2], th  = st[myoff + 3];
        const float tx0 = tcx - 0.5f * tw, ty0 = tcy - 0.5f * th;
        const float tx1 = tcx + 0.5f * tw, ty1 = tcy + 0.5f * th;
        bool any = false;
        for (int i = 0; i < MAXBOX; i++) {
            const float4 pb = s_pbox[sub][i];    // broadcast within warp (N=1)
            const float lx = fmaxf(pb.x, tx0);
            const float ly = fmaxf(pb.y, ty0);
            const float rx = fminf(pb.z, tx1);
            const float ry = fminf(pb.w, ty1);
            if (rx > lx && ry > ly) { any = true; break; }
        }
        if (any) {
            const float dx = sp[myoff + 0] - st[myoff + 0];
            const float dy = sp[myoff + 1] - st[myoff + 1];
            const float dw = sqrtf(sp[myoff + 2]) - sqrtf(st[myoff + 2]);
            const float dh = sqrtf(sp[myoff + 3]) - sqrtf(st[myoff + 3]);
            const float dc = sp[myoff + 4] - st[myoff + 4];
            a_coord = dx * dx + dy * dy + dw * dw + dh * dh;
            a_obj   = dc * dc;
        }
    }

    // ---- deterministic reduction: warp shuffle + 8-warp smem stage ----
    #pragma unroll
    for (int o = 16; o > 0; o >>= 1) {
        a_noobj += __shfl_xor_sync(0xffffffffu, a_noobj, o);
        a_cls   += __shfl_xor_sync(0xffffffffu, a_cls,   o);
        a_coord += __shfl_xor_sync(0xffffffffu, a_coord, o);
        a_obj   += __shfl_xor_sync(0xffffffffu, a_obj,   o);
    }
    const int wid  = tid >> 5;
    const int lane = tid & 31;
    if (lane == 0) {
        s_red[0][wid] = a_noobj;
        s_red[1][wid] = a_cls;
        s_red[2][wid] = a_coord;
        s_red[3][wid] = a_obj;
    }
    __syncthreads();
    if (tid == 0) {
        float4 r = make_float4(0.f, 0.f, 0.f, 0.f);
        #pragma unroll
        for (int w = 0; w < 8; w++) {      // merges BOTH images of the pair
            r.x += s_red[0][w];
            r.y += s_red[1][w];
            r.z += s_red[2][w];
            r.w += s_red[3][w];
        }
        g_part4[blockIdx.x] = r;
    }
}

// Stage 2: 32 blocks, each reduces 128 float4 -> one double4 (multi-SM).
__global__ void __launch_bounds__(128)
yolo_k1b()
{
    __shared__ double s_red[4][4];
    const int t = threadIdx.x;
    const float4 v = g_part4[blockIdx.x * 128 + t];
    double n = (double)v.x, c = (double)v.y, co = (double)v.z, ob = (double)v.w;

    #pragma unroll
    for (int o = 16; o > 0; o >>= 1) {
        n  += __shfl_xor_sync(0xffffffffu, n,  o);
        c  += __shfl_xor_sync(0xffffffffu, c,  o);
        co += __shfl_xor_sync(0xffffffffu, co, o);
        ob += __shfl_xor_sync(0xffffffffu, ob, o);
    }
    const int wid  = t >> 5;
    const int lane = t & 31;
    if (lane == 0) {
        s_red[0][wid] = n;
        s_red[1][wid] = c;
        s_red[2][wid] = co;
        s_red[3][wid] = ob;
    }
    __syncthreads();
    if (t == 0) {
        double4 r;
        r.x = s_red[0][0] + s_red[0][1] + s_red[0][2] + s_red[0][3];
        r.y = s_red[1][0] + s_red[1][1] + s_red[1][2] + s_red[1][3];
        r.z = s_red[2][0] + s_red[2][1] + s_red[2][2] + s_red[2][3];
        r.w = s_red[3][0] + s_red[3][1] + s_red[3][2] + s_red[3][3];
        g_mid[blockIdx.x] = r;
    }
}

// Stage 3: one warp reads 32 double4 (1 KB) and finishes.
__global__ void __launch_bounds__(32)
yolo_k2(float* __restrict__ out)
{
    const int t = threadIdx.x;
    const double4 v = g_mid[t];
    double n = v.x, c = v.y, co = v.z, ob = v.w;

    #pragma unroll
    for (int o = 16; o > 0; o >>= 1) {
        n  += __shfl_xor_sync(0xffffffffu, n,  o);
        c  += __shfl_xor_sync(0xffffffffu, c,  o);
        co += __shfl_xor_sync(0xffffffffu, co, o);
        ob += __shfl_xor_sync(0xffffffffu, ob, o);
    }
    if (t == 0) {
        const double Bd      = (double)NB;
        const double cls_l   = c / Bd;
        const double obj_l   = (ob + 0.5 * n) / Bd;
        const double coord_l = co * 5.0 / Bd;
        out[0] = (float)(cls_l + obj_l + coord_l);
        out[1] = (float)cls_l;
        out[2] = (float)obj_l;
        out[3] = (float)coord_l;
    }
}

extern "C" void kernel_launch(void* const* d_in, const int* in_sizes, int n_in,
                              void* d_out, int out_size)
{
    const float* pred = (const float*)d_in[0];
    const float* targ = (const float*)d_in[1];
    float* out = (float*)d_out;

    yolo_k1 <<<NPART, 256>>>(pred, targ);
    yolo_k1b<<<NMID, 128>>>();
    yolo_k2 <<<1, 32>>>(out);
}